// round 16
// baseline (speedup 1.0000x reference)
#include <cuda_runtime.h>
#include <cuda_bf16.h>
#include <cstdint>

#define B_SZ   4096
#define NB     64
#define DIM    256
#define N_WR   1001
#define N_ZQ   1000
#define CNT_E  1000
#define HID    512

// -------- device globals (scratch; allocation-free per harness rules) -------
static __device__ float g_wn[N_WR * DIM];            // normalized hyperplanes
static __device__ float g_zc[N_ZQ * HID];            // W1@zq + b
static __device__ uint32_t g_w2f[65536];             // W2 bf16, MMA B-fragment order

// ---------------------------------------------------------------------------
// helpers
// ---------------------------------------------------------------------------
__device__ __forceinline__ uint32_t smem_u32(const void* p) {
    uint32_t a;
    asm("{ .reg .u64 t; cvta.to.shared.u64 t, %1; cvt.u32.u64 %0, t; }" : "=r"(a) : "l"(p));
    return a;
}
__device__ __forceinline__ float tanh_fast(float x) {
    float y; asm("tanh.approx.f32 %0, %1;" : "=f"(y) : "f"(x)); return y;
}

#define LDSM4(r, addr)                                                        \
    asm volatile("ldmatrix.sync.aligned.m8n8.x4.shared.b16 {%0,%1,%2,%3}, [%4];" \
        : "=r"((r)[0]), "=r"((r)[1]), "=r"((r)[2]), "=r"((r)[3]) : "r"(addr))

#define MMA16816(d, a, b0, b1)                                                \
    asm volatile("mma.sync.aligned.m16n8k16.row.col.f32.bf16.bf16.f32 "       \
        "{%0,%1,%2,%3}, {%4,%5,%6,%7}, {%8,%9}, {%0,%1,%2,%3};"               \
        : "+f"((d)[0]), "+f"((d)[1]), "+f"((d)[2]), "+f"((d)[3])              \
        : "r"((a)[0]), "r"((a)[1]), "r"((a)[2]), "r"((a)[3]), "r"(b0), "r"(b1))

// ---------------------------------------------------------------------------
// Prep kernel 1: normalize w_r rows (one warp per row)
// ---------------------------------------------------------------------------
__global__ void wn_kernel(const float* __restrict__ wr) {
    int r = blockIdx.x, lane = threadIdx.x;
    const float4* row = (const float4*)(wr + r * DIM);
    float4 a = row[lane], b = row[32 + lane];
    float ss = a.x*a.x + a.y*a.y + a.z*a.z + a.w*a.w
             + b.x*b.x + b.y*b.y + b.z*b.z + b.w*b.w;
#pragma unroll
    for (int o = 16; o; o >>= 1) ss += __shfl_xor_sync(~0u, ss, o);
    float inv = 1.0f / fmaxf(sqrtf(ss), 1e-12f);
    float4* out = (float4*)(g_wn + r * DIM);
    float4 oa = {a.x*inv, a.y*inv, a.z*inv, a.w*inv};
    float4 ob = {b.x*inv, b.y*inv, b.z*inv, b.w*inv};
    out[lane] = oa; out[32 + lane] = ob;
}

// ---------------------------------------------------------------------------
// Prep kernel 2: zc[q][o] = W1[o]·zq[q] + bias[o]
// ---------------------------------------------------------------------------
__global__ void zc_kernel(const float* __restrict__ W, const float* __restrict__ bias,
                          const float* __restrict__ zq) {
    __shared__ float zs[4][DIM];
    int q0 = blockIdx.x * 4, tid = threadIdx.x;
#pragma unroll
    for (int qq = 0; qq < 4; ++qq) zs[qq][tid] = zq[(q0 + qq) * DIM + tid];
    __syncthreads();
    int warp = tid >> 5, lane = tid & 31;
    for (int o = warp; o < HID; o += 8) {
        const float4* Wr = (const float4*)(W + (size_t)o * HID);
        float4 w0 = Wr[lane], w1 = Wr[32 + lane];
        float p[4];
#pragma unroll
        for (int qq = 0; qq < 4; ++qq) {
            const float4* z4 = (const float4*)zs[qq];
            float4 z0 = z4[lane], z1 = z4[32 + lane];
            p[qq] = w0.x*z0.x + w0.y*z0.y + w0.z*z0.z + w0.w*z0.w
                  + w1.x*z1.x + w1.y*z1.y + w1.z*z1.z + w1.w*z1.w;
        }
#pragma unroll
        for (int off = 16; off; off >>= 1)
#pragma unroll
            for (int qq = 0; qq < 4; ++qq) p[qq] += __shfl_xor_sync(~0u, p[qq], off);
        if (lane == 0) {
            float bo = bias[o];
#pragma unroll
            for (int qq = 0; qq < 4; ++qq) g_zc[(q0 + qq) * HID + o] = p[qq] + bo;
        }
    }
}

// ---------------------------------------------------------------------------
// Prep kernel 3: pack W2 into per-warp MMA B-fragment streams.
// uint4 index u = w*2048 + ks*128 + r4*32 + lane  (w = n-warp 0..7, ks 0..15,
// r4 0..3, lane 0..31); word e of u (e 0..3):
//   jn = r4*2 + (e>>1),  n = w*64 + jn*8 + lane/4,  k = ks*16 + (e&1)*8 + 2*(lane&3)
//   value = bf16x2( W2[n][k], W2[n][k+1] )
// Each (w,ks,r4) LDG.128 across a warp is 512 B contiguous.
// ---------------------------------------------------------------------------
__global__ void w2frag_kernel(const float* __restrict__ W) {
    int gid = blockIdx.x * 256 + threadIdx.x;    // 0..65535, one b32 word each
    int e    = gid & 3;
    int u    = gid >> 2;
    int lane = u & 31;
    int r4   = (u >> 5) & 3;
    int ks   = (u >> 7) & 15;
    int w    = u >> 11;                          // 0..7
    int jn = r4 * 2 + (e >> 1);
    int n  = w * 64 + jn * 8 + (lane >> 2);
    int k  = ks * 16 + (e & 1) * 8 + (lane & 3) * 2;
    float v0 = W[(size_t)n * HID + DIM + k];
    float v1 = W[(size_t)n * HID + DIM + k + 1];
    __nv_bfloat162 pk = __floats2bfloat162_rn(v0, v1);
    g_w2f[gid] = *(uint32_t*)&pk;
}

// ---------------------------------------------------------------------------
// Main kernel: ONE batch per CTA, 256 threads, warp tile 64m x 64n (1m x 8n
// warp grid). Single N pass: A fragments LDSMed ONCE per ks, B streamed from
// L2 with +1-ks register prefetch. No barriers inside Phase B.
// SMEM (bytes):
//   EA [64][264 bf16] (stride 528)  0 .. 33792
//   ZC 33792(2KB) UA 35840(2KB)
//   DV 37888 RID 38144 LG 38400 AT 38656 CA 38912 CB 39168
//   PART [64][8] f32 39424 .. 41472
// ---------------------------------------------------------------------------
#define RSTRIDE   528
#define OFF_EA    0
#define OFF_ZC    33792
#define OFF_UA    35840
#define OFF_DV    37888
#define OFF_RID   38144
#define OFF_LG    38400
#define OFF_AT    38656
#define OFF_CA    38912
#define OFF_CB    39168
#define OFF_PART  39424
#define SMEM_BYTES 41472

#define NT 256

__global__ __launch_bounds__(NT, 1)
void enc_attn_kernel(const int*   __restrict__ rid_g,
                     const float* __restrict__ e_g,
                     const float* __restrict__ rw_g,
                     const int*   __restrict__ qrid_g,
                     const float* __restrict__ ua_g,
                     float*       __restrict__ out_g) {
    extern __shared__ char sm[];
    uint32_t smb = smem_u32(sm);

    float* ZC  = (float*)(sm + OFF_ZC);
    float* UA  = (float*)(sm + OFF_UA);
    float* DV  = (float*)(sm + OFF_DV);
    int*   RID = (int*)  (sm + OFF_RID);
    float* LG  = (float*)(sm + OFF_LG);
    float* AT  = (float*)(sm + OFF_AT);
    float* CA  = (float*)(sm + OFF_CA);
    float* CB  = (float*)(sm + OFF_CB);
    float* PART= (float*)(sm + OFF_PART);

    int tid = threadIdx.x, w = tid >> 5, lane = tid & 31;
    int b = blockIdx.x;

    // ---- Phase A: TransH projection; rids upfront, 2 groups of 4 batched rows
    {
        int rid8[8];
#pragma unroll
        for (int k = 0; k < 8; ++k) rid8[k] = rid_g[b * NB + w + k * 8];

#pragma unroll
        for (int gp = 0; gp < 2; ++gp) {
            float4 ev[4][2], wv[4][2];
#pragma unroll
            for (int k = 0; k < 4; ++k) {
                int row = w + (gp * 4 + k) * 8;
                const float4* ea = (const float4*)(e_g + ((size_t)b * NB + row) * DIM);
                ev[k][0] = ea[2 * lane]; ev[k][1] = ea[2 * lane + 1];
            }
#pragma unroll
            for (int k = 0; k < 4; ++k) {
                const float4* wa = (const float4*)(g_wn + (size_t)rid8[gp * 4 + k] * DIM);
                wv[k][0] = wa[2 * lane]; wv[k][1] = wa[2 * lane + 1];
            }
            float d[4];
#pragma unroll
            for (int k = 0; k < 4; ++k) {
                d[k] = ev[k][0].x*wv[k][0].x + ev[k][0].y*wv[k][0].y
                     + ev[k][0].z*wv[k][0].z + ev[k][0].w*wv[k][0].w
                     + ev[k][1].x*wv[k][1].x + ev[k][1].y*wv[k][1].y
                     + ev[k][1].z*wv[k][1].z + ev[k][1].w*wv[k][1].w;
            }
#pragma unroll
            for (int o = 16; o; o >>= 1)
#pragma unroll
                for (int k = 0; k < 4; ++k) d[k] += __shfl_xor_sync(~0u, d[k], o);
#pragma unroll
            for (int k = 0; k < 4; ++k) {
                int row = w + (gp * 4 + k) * 8;
                int r = rid8[gp * 4 + k];
                float m = (r < CNT_E) ? 1.0f : 0.0f;
                float dk = d[k];
                __nv_bfloat162 p0 = __floats2bfloat162_rn((ev[k][0].x - dk*wv[k][0].x)*m,
                                                          (ev[k][0].y - dk*wv[k][0].y)*m);
                __nv_bfloat162 p1 = __floats2bfloat162_rn((ev[k][0].z - dk*wv[k][0].z)*m,
                                                          (ev[k][0].w - dk*wv[k][0].w)*m);
                __nv_bfloat162 p2 = __floats2bfloat162_rn((ev[k][1].x - dk*wv[k][1].x)*m,
                                                          (ev[k][1].y - dk*wv[k][1].y)*m);
                __nv_bfloat162 p3 = __floats2bfloat162_rn((ev[k][1].z - dk*wv[k][1].z)*m,
                                                          (ev[k][1].w - dk*wv[k][1].w)*m);
                uint4 pk;
                pk.x = *(uint32_t*)&p0; pk.y = *(uint32_t*)&p1;
                pk.z = *(uint32_t*)&p2; pk.w = *(uint32_t*)&p3;
                *(uint4*)(sm + OFF_EA + row * RSTRIDE + lane * 16) = pk;
                if (lane == 0) { DV[row] = dk; RID[row] = r; }
            }
        }
    }
    {
        int q = qrid_g[b];
        for (int o = tid; o < HID; o += NT) {
            ZC[o] = g_zc[(size_t)q * HID + o];
            UA[o] = ua_g[o];
        }
    }
    __syncthreads();          // EA/ZC/UA visible

    // ---- Phase B: single pass, 64m x 64n per warp; A once, B prefetched ----
    uint32_t rowA[4];
#pragma unroll
    for (int mt = 0; mt < 4; ++mt)
        rowA[mt] = smb + OFF_EA + (mt * 16 + (lane & 15)) * RSTRIDE + (lane >> 4) * 16;

    const uint4* bb = (const uint4*)g_w2f + (size_t)w * 2048 + lane;

    float acc[4][8][4];
#pragma unroll
    for (int mt = 0; mt < 4; ++mt)
#pragma unroll
        for (int jn = 0; jn < 8; ++jn)
#pragma unroll
            for (int e = 0; e < 4; ++e) acc[mt][jn][e] = 0.f;

    uint4 bcur[4];
#pragma unroll
    for (int j = 0; j < 4; ++j) bcur[j] = __ldg(bb + j * 32);

#pragma unroll
    for (int ks = 0; ks < 16; ++ks) {
        uint4 bnxt[4];
        if (ks < 15) {
#pragma unroll
            for (int j = 0; j < 4; ++j) bnxt[j] = __ldg(bb + (ks + 1) * 128 + j * 32);
        }
        uint32_t kb = ks * 32;
        uint32_t a[4][4];
#pragma unroll
        for (int mt = 0; mt < 4; ++mt) LDSM4(a[mt], rowA[mt] + kb);
#pragma unroll
        for (int mt = 0; mt < 4; ++mt) {
            MMA16816(acc[mt][0], a[mt], bcur[0].x, bcur[0].y);
            MMA16816(acc[mt][1], a[mt], bcur[0].z, bcur[0].w);
            MMA16816(acc[mt][2], a[mt], bcur[1].x, bcur[1].y);
            MMA16816(acc[mt][3], a[mt], bcur[1].z, bcur[1].w);
            MMA16816(acc[mt][4], a[mt], bcur[2].x, bcur[2].y);
            MMA16816(acc[mt][5], a[mt], bcur[2].z, bcur[2].w);
            MMA16816(acc[mt][6], a[mt], bcur[3].x, bcur[3].y);
            MMA16816(acc[mt][7], a[mt], bcur[3].z, bcur[3].w);
        }
        if (ks < 15) {
#pragma unroll
            for (int j = 0; j < 4; ++j) bcur[j] = bnxt[j];
        }
    }

    // ---- fused epilogue: p[mt*2+h] += ua * tanh(v + zc) over this warp's cols
    float p[8];
#pragma unroll
    for (int k = 0; k < 8; ++k) p[k] = 0.f;
    {
        int cb0 = w * 64 + (lane & 3) * 2;
#pragma unroll
        for (int jn = 0; jn < 8; ++jn) {
            int col0 = cb0 + jn * 8;
            float2 zc2 = *(const float2*)(ZC + col0);
            float2 ua2 = *(const float2*)(UA + col0);
#pragma unroll
            for (int mt = 0; mt < 4; ++mt) {
                float h0 = tanh_fast(acc[mt][jn][0] + zc2.x);
                float h1 = tanh_fast(acc[mt][jn][1] + zc2.y);
                float h2 = tanh_fast(acc[mt][jn][2] + zc2.x);
                float h3 = tanh_fast(acc[mt][jn][3] + zc2.y);
                p[mt * 2 + 0] += fmaf(ua2.x, h0, ua2.y * h1);
                p[mt * 2 + 1] += fmaf(ua2.x, h2, ua2.y * h3);
            }
        }
    }
    // reduce across the 4 lanes sharing each row
#pragma unroll
    for (int o = 1; o <= 2; o <<= 1)
#pragma unroll
        for (int k = 0; k < 8; ++k) p[k] += __shfl_xor_sync(~0u, p[k], o);
    if ((lane & 3) == 0) {
#pragma unroll
        for (int mt = 0; mt < 4; ++mt)
#pragma unroll
            for (int h = 0; h < 2; ++h) {
                int row = mt * 16 + h * 8 + (lane >> 2);
                PART[row * 8 + w] = p[mt * 2 + h];
            }
    }
    __syncthreads();

    if (tid < 64) {
        const float* pr = PART + tid * 8;
        float s = pr[0] + pr[1] + pr[2] + pr[3] + pr[4] + pr[5] + pr[6] + pr[7];
        if (RID[tid] == CNT_E) s -= 1e19f;
        LG[tid] = s;
    }
    __syncthreads();

    // ---- softmax + rw (warp 0) ----
    if (tid < 32) {
        float x0 = LG[lane], x1 = LG[32 + lane];
        float mx = fmaxf(x0, x1);
#pragma unroll
        for (int o = 16; o; o >>= 1) mx = fmaxf(mx, __shfl_xor_sync(~0u, mx, o));
        float ex0 = __expf(x0 - mx), ex1 = __expf(x1 - mx);
        float s = ex0 + ex1;
#pragma unroll
        for (int o = 16; o; o >>= 1) s += __shfl_xor_sync(~0u, s, o);
        float inv = 1.0f / s;
        AT[lane]      = ex0 * inv + rw_g[b * NB + lane];
        AT[32 + lane] = ex1 * inv + rw_g[b * NB + 32 + lane];
    }
    __syncthreads();
    if (tid < 64) {
        int r = RID[tid];
        float m = (r < CNT_E) ? 1.0f : 0.0f;
        float a = AT[tid] * m;
        CA[tid] = a;
        CB[tid] = a * DV[tid];
    }
    __syncthreads();

    // ---- Phase D: out[d] = sum_n CA*e - CB*wn  (256 threads = 256 dims) ----
    {
        const float* eb = e_g + (size_t)b * NB * DIM + tid;
        float acc2 = 0.0f;
#pragma unroll 16
        for (int n = 0; n < 64; ++n) {
            float ca = CA[n], cb = CB[n];
            acc2 += ca * eb[n * DIM] - cb * g_wn[(size_t)RID[n] * DIM + tid];
        }
        out_g[(size_t)b * DIM + tid] = acc2;
    }
}

// ---------------------------------------------------------------------------
extern "C" void kernel_launch(void* const* d_in, const int* in_sizes, int n_in,
                              void* d_out, int out_size) {
    const int*   rid  = (const int*)d_in[0];
    const float* e    = (const float*)d_in[1];
    const float* rw   = (const float*)d_in[2];
    const int*   qrid = (const int*)d_in[3];
    const float* wr   = (const float*)d_in[4];
    const float* zq   = (const float*)d_in[5];
    const float* W    = (const float*)d_in[6];
    const float* Wb   = (const float*)d_in[7];
    const float* ua   = (const float*)d_in[8];
    float* out = (float*)d_out;

    static bool attr_set = false;
    if (!attr_set) {
        cudaFuncSetAttribute(enc_attn_kernel,
                             cudaFuncAttributeMaxDynamicSharedMemorySize, SMEM_BYTES);
        attr_set = true;
    }

    wn_kernel<<<N_WR, 32>>>(wr);
    zc_kernel<<<N_ZQ / 4, 256>>>(W, Wb, zq);
    w2frag_kernel<<<256, 256>>>(W);
    enc_attn_kernel<<<B_SZ, NT, SMEM_BYTES>>>(rid, e, rw, qrid, ua, out);
}

// round 17
// speedup vs baseline: 1.0258x; 1.0258x over previous
#include <cuda_runtime.h>
#include <cuda_bf16.h>
#include <cstdint>

#define B_SZ   4096
#define NB     64
#define DIM    256
#define N_WR   1001
#define N_ZQ   1000
#define CNT_E  1000
#define HID    512

// -------- device globals (scratch; allocation-free per harness rules) -------
static __device__ float g_wn[N_WR * DIM];            // normalized hyperplanes
static __device__ float g_zc[N_ZQ * HID];            // W1@zq + b
static __device__ uint32_t g_w2f[65536];             // W2 bf16, MMA B-fragment order

// ---------------------------------------------------------------------------
// helpers
// ---------------------------------------------------------------------------
__device__ __forceinline__ uint32_t smem_u32(const void* p) {
    uint32_t a;
    asm("{ .reg .u64 t; cvta.to.shared.u64 t, %1; cvt.u32.u64 %0, t; }" : "=r"(a) : "l"(p));
    return a;
}
__device__ __forceinline__ float tanh_fast(float x) {
    float y; asm("tanh.approx.f32 %0, %1;" : "=f"(y) : "f"(x)); return y;
}

#define LDSM4(r, addr)                                                        \
    asm volatile("ldmatrix.sync.aligned.m8n8.x4.shared.b16 {%0,%1,%2,%3}, [%4];" \
        : "=r"((r)[0]), "=r"((r)[1]), "=r"((r)[2]), "=r"((r)[3]) : "r"(addr))

#define MMA16816(d, a, b0, b1)                                                \
    asm volatile("mma.sync.aligned.m16n8k16.row.col.f32.bf16.bf16.f32 "       \
        "{%0,%1,%2,%3}, {%4,%5,%6,%7}, {%8,%9}, {%0,%1,%2,%3};"               \
        : "+f"((d)[0]), "+f"((d)[1]), "+f"((d)[2]), "+f"((d)[3])              \
        : "r"((a)[0]), "r"((a)[1]), "r"((a)[2]), "r"((a)[3]), "r"(b0), "r"(b1))

// ---------------------------------------------------------------------------
// Prep kernel 1: normalize w_r rows (one warp per row)
// ---------------------------------------------------------------------------
__global__ void wn_kernel(const float* __restrict__ wr) {
    int r = blockIdx.x, lane = threadIdx.x;
    const float4* row = (const float4*)(wr + r * DIM);
    float4 a = row[lane], b = row[32 + lane];
    float ss = a.x*a.x + a.y*a.y + a.z*a.z + a.w*a.w
             + b.x*b.x + b.y*b.y + b.z*b.z + b.w*b.w;
#pragma unroll
    for (int o = 16; o; o >>= 1) ss += __shfl_xor_sync(~0u, ss, o);
    float inv = 1.0f / fmaxf(sqrtf(ss), 1e-12f);
    float4* out = (float4*)(g_wn + r * DIM);
    float4 oa = {a.x*inv, a.y*inv, a.z*inv, a.w*inv};
    float4 ob = {b.x*inv, b.y*inv, b.z*inv, b.w*inv};
    out[lane] = oa; out[32 + lane] = ob;
}

// ---------------------------------------------------------------------------
// Prep kernel 2: zc[q][o] = W1[o]·zq[q] + bias[o]
// ---------------------------------------------------------------------------
__global__ void zc_kernel(const float* __restrict__ W, const float* __restrict__ bias,
                          const float* __restrict__ zq) {
    __shared__ float zs[4][DIM];
    int q0 = blockIdx.x * 4, tid = threadIdx.x;
#pragma unroll
    for (int qq = 0; qq < 4; ++qq) zs[qq][tid] = zq[(q0 + qq) * DIM + tid];
    __syncthreads();
    int warp = tid >> 5, lane = tid & 31;
    for (int o = warp; o < HID; o += 8) {
        const float4* Wr = (const float4*)(W + (size_t)o * HID);
        float4 w0 = Wr[lane], w1 = Wr[32 + lane];
        float p[4];
#pragma unroll
        for (int qq = 0; qq < 4; ++qq) {
            const float4* z4 = (const float4*)zs[qq];
            float4 z0 = z4[lane], z1 = z4[32 + lane];
            p[qq] = w0.x*z0.x + w0.y*z0.y + w0.z*z0.z + w0.w*z0.w
                  + w1.x*z1.x + w1.y*z1.y + w1.z*z1.z + w1.w*z1.w;
        }
#pragma unroll
        for (int off = 16; off; off >>= 1)
#pragma unroll
            for (int qq = 0; qq < 4; ++qq) p[qq] += __shfl_xor_sync(~0u, p[qq], off);
        if (lane == 0) {
            float bo = bias[o];
#pragma unroll
            for (int qq = 0; qq < 4; ++qq) g_zc[(q0 + qq) * HID + o] = p[qq] + bo;
        }
    }
}

// ---------------------------------------------------------------------------
// Prep kernel 3: pack W2 into per-warp (32-col slice) MMA B-fragment streams.
// Word gid: w = gid>>12 (0..15), ks = (gid>>8)&15, lane = (gid>>3)&31,
//           r = gid&7 with jn = r>>1, half = r&1.
//   n = w*32 + jn*8 + lane/4,  k = ks*16 + half*8 + 2*(lane&3)
//   value = bf16x2( W2[n][k], W2[n][k+1] )
// Thread "lane" of warp w reads 2 uint4 per ks: words [lane*8 .. lane*8+7].
// ---------------------------------------------------------------------------
__global__ void w2frag_kernel(const float* __restrict__ W) {
    int gid = blockIdx.x * 256 + threadIdx.x;    // 0..65535
    int r    = gid & 7;
    int lane = (gid >> 3) & 31;
    int ks   = (gid >> 8) & 15;
    int w    = gid >> 12;                        // 0..15
    int jn   = r >> 1, half = r & 1;
    int n = w * 32 + jn * 8 + (lane >> 2);
    int k = ks * 16 + half * 8 + (lane & 3) * 2;
    float v0 = W[(size_t)n * HID + DIM + k];
    float v1 = W[(size_t)n * HID + DIM + k + 1];
    __nv_bfloat162 pk = __floats2bfloat162_rn(v0, v1);
    g_w2f[gid] = *(uint32_t*)&pk;
}

// ---------------------------------------------------------------------------
// Main kernel: ONE batch per CTA, 512 threads (16 warps, 1m x 16n grid),
// warp tile 64m x 32n, single N pass, Phase B barrier-free.
// acc = 64 regs/thread -> ~120 total -> 16 warps/SM.
// SMEM (bytes):
//   EA [64][264 bf16] (stride 528)  0 .. 33792
//   ZC 33792(2KB) UA 35840(2KB)
//   DV 37888 RID 38144 LG 38400 AT 38656 CA 38912 CB 39168
//   PART [64][16] f32 39424 .. 43520   (reused as PD[512] in Phase D)
// ---------------------------------------------------------------------------
#define RSTRIDE   528
#define OFF_EA    0
#define OFF_ZC    33792
#define OFF_UA    35840
#define OFF_DV    37888
#define OFF_RID   38144
#define OFF_LG    38400
#define OFF_AT    38656
#define OFF_CA    38912
#define OFF_CB    39168
#define OFF_PART  39424
#define SMEM_BYTES 43520

#define NT 512

__global__ __launch_bounds__(NT, 1)
void enc_attn_kernel(const int*   __restrict__ rid_g,
                     const float* __restrict__ e_g,
                     const float* __restrict__ rw_g,
                     const int*   __restrict__ qrid_g,
                     const float* __restrict__ ua_g,
                     float*       __restrict__ out_g) {
    extern __shared__ char sm[];
    uint32_t smb = smem_u32(sm);

    float* ZC  = (float*)(sm + OFF_ZC);
    float* UA  = (float*)(sm + OFF_UA);
    float* DV  = (float*)(sm + OFF_DV);
    int*   RID = (int*)  (sm + OFF_RID);
    float* LG  = (float*)(sm + OFF_LG);
    float* AT  = (float*)(sm + OFF_AT);
    float* CA  = (float*)(sm + OFF_CA);
    float* CB  = (float*)(sm + OFF_CB);
    float* PART= (float*)(sm + OFF_PART);

    int tid = threadIdx.x, w = tid >> 5, lane = tid & 31;
    int b = blockIdx.x;

    // ---- Phase A: TransH projection; 4 rows per warp (rows w + k*16),
    //      all 16 float4 loads in flight before reductions ----
    {
        int rid4[4];
#pragma unroll
        for (int k = 0; k < 4; ++k) rid4[k] = rid_g[b * NB + w + k * 16];

        float4 ev[4][2], wv[4][2];
#pragma unroll
        for (int k = 0; k < 4; ++k) {
            int row = w + k * 16;
            const float4* ea = (const float4*)(e_g + ((size_t)b * NB + row) * DIM);
            ev[k][0] = ea[2 * lane]; ev[k][1] = ea[2 * lane + 1];
        }
#pragma unroll
        for (int k = 0; k < 4; ++k) {
            const float4* wa = (const float4*)(g_wn + (size_t)rid4[k] * DIM);
            wv[k][0] = wa[2 * lane]; wv[k][1] = wa[2 * lane + 1];
        }
        float d[4];
#pragma unroll
        for (int k = 0; k < 4; ++k) {
            d[k] = ev[k][0].x*wv[k][0].x + ev[k][0].y*wv[k][0].y
                 + ev[k][0].z*wv[k][0].z + ev[k][0].w*wv[k][0].w
                 + ev[k][1].x*wv[k][1].x + ev[k][1].y*wv[k][1].y
                 + ev[k][1].z*wv[k][1].z + ev[k][1].w*wv[k][1].w;
        }
#pragma unroll
        for (int o = 16; o; o >>= 1)
#pragma unroll
            for (int k = 0; k < 4; ++k) d[k] += __shfl_xor_sync(~0u, d[k], o);
#pragma unroll
        for (int k = 0; k < 4; ++k) {
            int row = w + k * 16;
            int r = rid4[k];
            float m = (r < CNT_E) ? 1.0f : 0.0f;
            float dk = d[k];
            __nv_bfloat162 p0 = __floats2bfloat162_rn((ev[k][0].x - dk*wv[k][0].x)*m,
                                                      (ev[k][0].y - dk*wv[k][0].y)*m);
            __nv_bfloat162 p1 = __floats2bfloat162_rn((ev[k][0].z - dk*wv[k][0].z)*m,
                                                      (ev[k][0].w - dk*wv[k][0].w)*m);
            __nv_bfloat162 p2 = __floats2bfloat162_rn((ev[k][1].x - dk*wv[k][1].x)*m,
                                                      (ev[k][1].y - dk*wv[k][1].y)*m);
            __nv_bfloat162 p3 = __floats2bfloat162_rn((ev[k][1].z - dk*wv[k][1].z)*m,
                                                      (ev[k][1].w - dk*wv[k][1].w)*m);
            uint4 pk;
            pk.x = *(uint32_t*)&p0; pk.y = *(uint32_t*)&p1;
            pk.z = *(uint32_t*)&p2; pk.w = *(uint32_t*)&p3;
            *(uint4*)(sm + OFF_EA + row * RSTRIDE + lane * 16) = pk;
            if (lane == 0) { DV[row] = dk; RID[row] = r; }
        }
    }
    {
        int q = qrid_g[b];
        for (int o = tid; o < HID; o += NT) {
            ZC[o] = g_zc[(size_t)q * HID + o];
            UA[o] = ua_g[o];
        }
    }
    __syncthreads();          // EA/ZC/UA visible

    // ---- Phase B: single pass; warp w owns all 64 rows x cols [w*32,w*32+32)
    uint32_t rowA[4];
#pragma unroll
    for (int mt = 0; mt < 4; ++mt)
        rowA[mt] = smb + OFF_EA + (mt * 16 + (lane & 15)) * RSTRIDE + (lane >> 4) * 16;

    // per-warp B stream: 2 uint4 per ks, base uint4 index w*1024 + ks*64 + lane*2
    const uint4* bb = (const uint4*)g_w2f + (size_t)w * 1024 + lane * 2;

    float acc[4][4][4];
#pragma unroll
    for (int mt = 0; mt < 4; ++mt)
#pragma unroll
        for (int jn = 0; jn < 4; ++jn)
#pragma unroll
            for (int e = 0; e < 4; ++e) acc[mt][jn][e] = 0.f;

    uint4 bc0 = __ldg(bb), bc1 = __ldg(bb + 1);

#pragma unroll
    for (int ks = 0; ks < 16; ++ks) {
        uint4 bn0, bn1;
        if (ks < 15) { bn0 = __ldg(bb + (ks + 1) * 64); bn1 = __ldg(bb + (ks + 1) * 64 + 1); }
        uint32_t kb = ks * 32;
        uint32_t a[4][4];
#pragma unroll
        for (int mt = 0; mt < 4; ++mt) LDSM4(a[mt], rowA[mt] + kb);
#pragma unroll
        for (int mt = 0; mt < 4; ++mt) {
            MMA16816(acc[mt][0], a[mt], bc0.x, bc0.y);
            MMA16816(acc[mt][1], a[mt], bc0.z, bc0.w);
            MMA16816(acc[mt][2], a[mt], bc1.x, bc1.y);
            MMA16816(acc[mt][3], a[mt], bc1.z, bc1.w);
        }
        if (ks < 15) { bc0 = bn0; bc1 = bn1; }
    }

    // ---- fused epilogue: p += ua * tanh(v + zc) over this warp's 32 cols ----
    float p[8];
#pragma unroll
    for (int k = 0; k < 8; ++k) p[k] = 0.f;
    {
        int cb0 = w * 32 + (lane & 3) * 2;
#pragma unroll
        for (int jn = 0; jn < 4; ++jn) {
            int col0 = cb0 + jn * 8;
            float2 zc2 = *(const float2*)(ZC + col0);
            float2 ua2 = *(const float2*)(UA + col0);
#pragma unroll
            for (int mt = 0; mt < 4; ++mt) {
                float h0 = tanh_fast(acc[mt][jn][0] + zc2.x);
                float h1 = tanh_fast(acc[mt][jn][1] + zc2.y);
                float h2 = tanh_fast(acc[mt][jn][2] + zc2.x);
                float h3 = tanh_fast(acc[mt][jn][3] + zc2.y);
                p[mt * 2 + 0] += fmaf(ua2.x, h0, ua2.y * h1);
                p[mt * 2 + 1] += fmaf(ua2.x, h2, ua2.y * h3);
            }
        }
    }
    // reduce across the 4 lanes sharing each row
#pragma unroll
    for (int o = 1; o <= 2; o <<= 1)
#pragma unroll
        for (int k = 0; k < 8; ++k) p[k] += __shfl_xor_sync(~0u, p[k], o);
    if ((lane & 3) == 0) {
#pragma unroll
        for (int mt = 0; mt < 4; ++mt)
#pragma unroll
            for (int h = 0; h < 2; ++h) {
                int row = mt * 16 + h * 8 + (lane >> 2);
                PART[row * 16 + w] = p[mt * 2 + h];
            }
    }
    __syncthreads();

    if (tid < 64) {
        const float* pr = PART + tid * 16;
        float s = 0.f;
#pragma unroll
        for (int j = 0; j < 16; ++j) s += pr[j];
        if (RID[tid] == CNT_E) s -= 1e19f;
        LG[tid] = s;
    }
    __syncthreads();

    // ---- softmax + rw (warp 0) ----
    if (tid < 32) {
        float x0 = LG[lane], x1 = LG[32 + lane];
        float mx = fmaxf(x0, x1);
#pragma unroll
        for (int o = 16; o; o >>= 1) mx = fmaxf(mx, __shfl_xor_sync(~0u, mx, o));
        float ex0 = __expf(x0 - mx), ex1 = __expf(x1 - mx);
        float s = ex0 + ex1;
#pragma unroll
        for (int o = 16; o; o >>= 1) s += __shfl_xor_sync(~0u, s, o);
        float inv = 1.0f / s;
        AT[lane]      = ex0 * inv + rw_g[b * NB + lane];
        AT[32 + lane] = ex1 * inv + rw_g[b * NB + 32 + lane];
    }
    __syncthreads();
    if (tid < 64) {
        int r = RID[tid];
        float m = (r < CNT_E) ? 1.0f : 0.0f;
        float a = AT[tid] * m;
        CA[tid] = a;
        CB[tid] = a * DV[tid];
    }
    __syncthreads();

    // ---- Phase D: 512 threads = 2 n-halves x 256 dims; SMEM combine ----
    {
        float* PD = PART;                   // reuse (free after LG)
        int h = tid >> 8, d = tid & 255;
        const float* eb = e_g + (size_t)b * NB * DIM + d;
        float acc2 = 0.0f;
        int n0 = h * 32;
#pragma unroll 16
        for (int n = n0; n < n0 + 32; ++n) {
            float ca = CA[n], cb = CB[n];
            acc2 += ca * eb[n * DIM] - cb * g_wn[(size_t)RID[n] * DIM + d];
        }
        PD[h * 256 + d] = acc2;
        __syncthreads();
        if (tid < 256) out_g[(size_t)b * DIM + tid] = PD[tid] + PD[256 + tid];
    }
}

// ---------------------------------------------------------------------------
extern "C" void kernel_launch(void* const* d_in, const int* in_sizes, int n_in,
                              void* d_out, int out_size) {
    const int*   rid  = (const int*)d_in[0];
    const float* e    = (const float*)d_in[1];
    const float* rw   = (const float*)d_in[2];
    const int*   qrid = (const int*)d_in[3];
    const float* wr   = (const float*)d_in[4];
    const float* zq   = (const float*)d_in[5];
    const float* W    = (const float*)d_in[6];
    const float* Wb   = (const float*)d_in[7];
    const float* ua   = (const float*)d_in[8];
    float* out = (float*)d_out;

    static bool attr_set = false;
    if (!attr_set) {
        cudaFuncSetAttribute(enc_attn_kernel,
                             cudaFuncAttributeMaxDynamicSharedMemorySize, SMEM_BYTES);
        attr_set = true;
    }

    wn_kernel<<<N_WR, 32>>>(wr);
    zc_kernel<<<N_ZQ / 4, 256>>>(W, Wb, zq);
    w2frag_kernel<<<256, 256>>>(W);
    enc_attn_kernel<<<B_SZ, NT, SMEM_BYTES>>>(rid, e, rw, qrid, ua, out);
}